// round 4
// baseline (speedup 1.0000x reference)
#include <cuda_runtime.h>

#define NT 256
#define PA 194            // pitch (floats) for A, Q, K, V  (even -> LDS.64 aligned)
#define PS 65             // S pitch
#define POH 34            // per-head O pitch
#define PWST 18           // weight stage pitch (16-col chunks)

#define OFF_A   0         // 64 x PA : X, then Y, then relu(M)
#define OFF_Q   12416     // 64 x PA : full scaled Q, later merge2 output T
#define OFF_K   24832     // 64 x PA : full K (per branch)
#define OFF_V   37248     // 64 x PA : full V (per branch)
#define OFF_S   49664     // 64 x PS
#define OFF_OH  53824     // 64 x POH
#define OFF_WST 56000     // 96 x PWST = 1728
#define SMEM_FLOATS 57728 // 230912 bytes

typedef unsigned long long u64;

__device__ __forceinline__ u64 pk2(float lo, float hi) {
    u64 r; asm("mov.b64 %0,{%1,%2};" : "=l"(r) : "f"(lo), "f"(hi)); return r;
}
__device__ __forceinline__ void upk2(u64 v, float& lo, float& hi) {
    asm("mov.b64 {%0,%1}, %2;" : "=f"(lo), "=f"(hi) : "l"(v));
}
__device__ __forceinline__ void fma2(u64& d, u64 a, u64 b) {
    asm("fma.rn.f32x2 %0, %1, %2, %0;" : "+l"(d) : "l"(a), "l"(b));
}

__device__ float g_bias[2 * 6 * 64 * 64];

__global__ void bias_pre_kernel(const float* __restrict__ rpb_x,
                                const float* __restrict__ rpb_y,
                                const int* __restrict__ rel_idx) {
    int i = blockIdx.x * blockDim.x + threadIdx.x;
    if (i >= 2 * 6 * 4096) return;
    int br = i / (6 * 4096);
    int h  = (i / 4096) % 6;
    int nm = i & 4095;
    const float* tab = br ? rpb_y : rpb_x;
    g_bias[i] = tab[rel_idx[nm] * 6 + h];
}

// Output: 64 x 192.  Reduction K = 192 over source [64][PA] (c-contiguous).
// W is row-major [o][192] (o = output col).  Packs reduction pairs -> both
// operands are contiguous LDS.64; A-loads are warp-uniform broadcasts.
__device__ __forceinline__ void wide_gemm(
    float* sm, int srcOff,
    const float* __restrict__ Wg, const float* __restrict__ bg,
    float scl, float* dstS, float* __restrict__ dstG, int t)
{
    const int tr = t >> 5, tc = t & 31;
    const int n0 = tr * 8;
    #pragma unroll 1
    for (int half = 0; half < 2; ++half) {
        u64 acc[8][3];
        #pragma unroll
        for (int i = 0; i < 8; ++i)
            #pragma unroll
            for (int j = 0; j < 3; ++j) acc[i][j] = 0ULL;
        #pragma unroll 1
        for (int ch = 0; ch < 12; ++ch) {
            // stage 96 W-rows x 16 cols, plain copy (coalesced both sides)
            #pragma unroll
            for (int i = t; i < 1536; i += NT) {
                int jj = i >> 4, dd = i & 15;
                sm[OFF_WST + jj * PWST + dd] = Wg[(half * 96 + jj) * 192 + ch * 16 + dd];
            }
            __syncthreads();
            const float* sa = sm + srcOff + ch * 16;
            #pragma unroll
            for (int dp = 0; dp < 8; ++dp) {
                u64 a2[8], w2[3];
                #pragma unroll
                for (int i = 0; i < 8; ++i)
                    a2[i] = *reinterpret_cast<const u64*>(&sa[(n0 + i) * PA + 2 * dp]);
                #pragma unroll
                for (int j = 0; j < 3; ++j)
                    w2[j] = *reinterpret_cast<const u64*>(
                        &sm[OFF_WST + (tc * 3 + j) * PWST + 2 * dp]);
                #pragma unroll
                for (int i = 0; i < 8; ++i)
                    #pragma unroll
                    for (int j = 0; j < 3; ++j)
                        fma2(acc[i][j], a2[i], w2[j]);
            }
            __syncthreads();
        }
        #pragma unroll
        for (int j = 0; j < 3; ++j) {
            const int o = half * 96 + tc * 3 + j;
            const float b = bg[o];
            #pragma unroll
            for (int i = 0; i < 8; ++i) {
                float lo, hi; upk2(acc[i][j], lo, hi);
                float v = (lo + hi + b) * scl;
                if (dstG) dstG[(n0 + i) * 192 + o] = v;
                else      dstS[(n0 + i) * PA + o] = v;
            }
        }
    }
}

__global__ void __launch_bounds__(NT, 1) fused_attn_kernel(
    const float* __restrict__ x, const float* __restrict__ y,
    const float* __restrict__ mask_x, const float* __restrict__ mask_y,
    const float* __restrict__ qkv_w, const float* __restrict__ qkv_b,
    const float* __restrict__ kv_w, const float* __restrict__ kv_b,
    const float* __restrict__ merge1_w, const float* __restrict__ merge1_b,
    const float* __restrict__ merge2_w, const float* __restrict__ merge2_b,
    const float* __restrict__ proj_w, const float* __restrict__ proj_b,
    float* __restrict__ out)
{
    extern __shared__ float sm[];
    const int t = threadIdx.x;
    const int w = blockIdx.x;
    const int tr = t >> 5, tc = t & 31;    // wide-phase mapping
    const int n0 = tr * 8;
    const float scale = 0.17677669529663687f;  // 32^-0.5

    // merge1 accumulator in registers; cols = half*96 + tc*3 + j
    float M[8][6];
    #pragma unroll
    for (int half = 0; half < 2; ++half)
        #pragma unroll
        for (int j = 0; j < 3; ++j) {
            float b = merge1_b[half * 96 + tc * 3 + j];
            #pragma unroll
            for (int i = 0; i < 8; ++i) M[i][half * 3 + j] = b;
        }

    #pragma unroll 1
    for (int br = 0; br < 2; ++br) {
        // ---- load activation (X or Y) ----
        {
            const float* ap = (br ? y : x) + (size_t)w * 12288;
            for (int i = t; i < 12288; i += NT) {
                int n = i / 192, c = i - n * 192;
                sm[OFF_A + n * PA + c] = ap[i];
            }
        }
        // ---- projections (wide_gemm's internal stage-sync orders the load) ----
        if (br == 0) {
            wide_gemm(sm, OFF_A, qkv_w,             qkv_b,       scale, sm + OFF_Q, nullptr, t);
            wide_gemm(sm, OFF_A, qkv_w + 192 * 192, qkv_b + 192, 1.f,   sm + OFF_K, nullptr, t);
            wide_gemm(sm, OFF_A, qkv_w + 384 * 192, qkv_b + 384, 1.f,   sm + OFF_V, nullptr, t);
        } else {
            wide_gemm(sm, OFF_A, kv_w,              kv_b,        1.f,   sm + OFF_K, nullptr, t);
            wide_gemm(sm, OFF_A, kv_w + 192 * 192,  kv_b + 192,  1.f,   sm + OFF_V, nullptr, t);
        }
        __syncthreads();

        const float* bias_base = g_bias + (size_t)(br * 6) * 4096;
        const float* maskp = (br ? mask_y : mask_x) + (size_t)(w & 1023) * 4096;

        #pragma unroll 1
        for (int h = 0; h < 6; ++h) {
            const int h32 = h * 32;

            // ---- S = Q K^T + bias + mask  (8x2 tiles, packed over d) ----
            {
                const int m0 = tc * 2;
                float bi[8][2], mk[8][2];
                const float* bb = bias_base + h * 4096;
                #pragma unroll
                for (int i = 0; i < 8; ++i)
                    #pragma unroll
                    for (int j = 0; j < 2; ++j) {
                        bi[i][j] = bb[(n0 + i) * 64 + m0 + j];
                        mk[i][j] = maskp[(n0 + i) * 64 + m0 + j];
                    }
                u64 acc[8][2];
                #pragma unroll
                for (int i = 0; i < 8; ++i) { acc[i][0] = 0ULL; acc[i][1] = 0ULL; }
                #pragma unroll
                for (int dp = 0; dp < 16; ++dp) {
                    u64 q2[8], k2[2];
                    #pragma unroll
                    for (int i = 0; i < 8; ++i)
                        q2[i] = *reinterpret_cast<const u64*>(
                            &sm[OFF_Q + (n0 + i) * PA + h32 + 2 * dp]);
                    #pragma unroll
                    for (int j = 0; j < 2; ++j)
                        k2[j] = *reinterpret_cast<const u64*>(
                            &sm[OFF_K + (m0 + j) * PA + h32 + 2 * dp]);
                    #pragma unroll
                    for (int i = 0; i < 8; ++i)
                        #pragma unroll
                        for (int j = 0; j < 2; ++j)
                            fma2(acc[i][j], q2[i], k2[j]);
                }
                #pragma unroll
                for (int i = 0; i < 8; ++i)
                    #pragma unroll
                    for (int j = 0; j < 2; ++j) {
                        float lo, hi; upk2(acc[i][j], lo, hi);
                        sm[OFF_S + (n0 + i) * PS + m0 + j] = lo + hi + bi[i][j] + mk[i][j];
                    }
            }
            __syncthreads();

            // ---- softmax per row (warp handles 8 rows) ----
            {
                const int wi = t >> 5, l = t & 31;
                #pragma unroll
                for (int rr = 0; rr < 8; rr++) {
                    int r = wi * 8 + rr;
                    float v0 = sm[OFF_S + r * PS + l];
                    float v1 = sm[OFF_S + r * PS + 32 + l];
                    float mx = fmaxf(v0, v1);
                    #pragma unroll
                    for (int o = 16; o > 0; o >>= 1)
                        mx = fmaxf(mx, __shfl_xor_sync(0xffffffffu, mx, o));
                    float e0 = __expf(v0 - mx), e1 = __expf(v1 - mx);
                    float s = e0 + e1;
                    #pragma unroll
                    for (int o = 16; o > 0; o >>= 1)
                        s += __shfl_xor_sync(0xffffffffu, s, o);
                    float inv = 1.0f / s;
                    sm[OFF_S + r * PS + l]      = e0 * inv;
                    sm[OFF_S + r * PS + 32 + l] = e1 * inv;
                }
            }
            __syncthreads();

            // ---- O_h = P V_h  (4 rows x 1 u64-col per thread, packed over d) ----
            {
                const int n0p = (t >> 4) * 4, d0 = (t & 15) * 2;
                u64 acc[4];
                #pragma unroll
                for (int i = 0; i < 4; ++i) acc[i] = 0ULL;
                #pragma unroll 4
                for (int m = 0; m < 64; ++m) {
                    u64 v2 = *reinterpret_cast<const u64*>(
                        &sm[OFF_V + m * PA + h32 + d0]);
                    #pragma unroll
                    for (int i = 0; i < 4; ++i) {
                        float p = sm[OFF_S + (n0p + i) * PS + m];
                        fma2(acc[i], pk2(p, p), v2);
                    }
                }
                #pragma unroll
                for (int i = 0; i < 4; ++i)
                    *reinterpret_cast<u64*>(&sm[OFF_OH + (n0p + i) * POH + d0]) = acc[i];
            }
            __syncthreads();

            // ---- M += O_h @ W1_slice^T  (wide mapping, reduction d=32) ----
            {
                #pragma unroll 1
                for (int half = 0; half < 2; ++half) {
                    u64 acc[8][3];
                    #pragma unroll
                    for (int i = 0; i < 8; ++i)
                        #pragma unroll
                        for (int j = 0; j < 3; ++j) acc[i][j] = 0ULL;
                    #pragma unroll 1
                    for (int dc = 0; dc < 2; ++dc) {
                        #pragma unroll
                        for (int i = t; i < 1536; i += NT) {
                            int jj = i >> 4, dd = i & 15;
                            sm[OFF_WST + jj * PWST + dd] =
                                merge1_w[(half * 96 + jj) * 384 + br * 192 + h32 + dc * 16 + dd];
                        }
                        __syncthreads();
                        #pragma unroll
                        for (int dp = 0; dp < 8; ++dp) {
                            u64 o2[8], w2[3];
                            #pragma unroll
                            for (int i = 0; i < 8; ++i)
                                o2[i] = *reinterpret_cast<const u64*>(
                                    &sm[OFF_OH + (n0 + i) * POH + dc * 16 + 2 * dp]);
                            #pragma unroll
                            for (int j = 0; j < 3; ++j)
                                w2[j] = *reinterpret_cast<const u64*>(
                                    &sm[OFF_WST + (tc * 3 + j) * PWST + 2 * dp]);
                            #pragma unroll
                            for (int i = 0; i < 8; ++i)
                                #pragma unroll
                                for (int j = 0; j < 3; ++j)
                                    fma2(acc[i][j], o2[i], w2[j]);
                        }
                        __syncthreads();
                    }
                    #pragma unroll
                    for (int i = 0; i < 8; ++i)
                        #pragma unroll
                        for (int j = 0; j < 3; ++j) {
                            float lo, hi; upk2(acc[i][j], lo, hi);
                            M[i][half * 3 + j] += lo + hi;
                        }
                }
            }
        }  // heads
    }  // branches

    // ---- leaky relu(M) -> OFF_A (A is dead) ----
    #pragma unroll
    for (int half = 0; half < 2; ++half)
        #pragma unroll
        for (int j = 0; j < 3; ++j)
            #pragma unroll
            for (int i = 0; i < 8; ++i) {
                float v = M[i][half * 3 + j];
                v = v > 0.f ? v : 0.2f * v;
                sm[OFF_A + (n0 + i) * PA + half * 96 + tc * 3 + j] = v;
            }
    // merge2: T = relu(M) @ W2^T + b2  -> OFF_Q  (internal stage-sync orders writes)
    wide_gemm(sm, OFF_A, merge2_w, merge2_b, 1.f, sm + OFF_Q, nullptr, t);
    // proj: out = T @ Wp^T + pb -> global
    wide_gemm(sm, OFF_Q, proj_w, proj_b, 1.f, nullptr, out + (size_t)w * 12288, t);
}

extern "C" void kernel_launch(void* const* d_in, const int* in_sizes, int n_in,
                              void* d_out, int out_size) {
    const float* x        = (const float*)d_in[0];
    const float* y        = (const float*)d_in[1];
    const float* mask_x   = (const float*)d_in[2];
    const float* mask_y   = (const float*)d_in[3];
    const float* qkv_w    = (const float*)d_in[4];
    const float* qkv_b    = (const float*)d_in[5];
    const float* kv_w     = (const float*)d_in[6];
    const float* kv_b     = (const float*)d_in[7];
    const float* rpb_x    = (const float*)d_in[8];
    const float* rpb_y    = (const float*)d_in[9];
    const float* merge1_w = (const float*)d_in[10];
    const float* merge1_b = (const float*)d_in[11];
    const float* merge2_w = (const float*)d_in[12];
    const float* merge2_b = (const float*)d_in[13];
    const float* proj_w   = (const float*)d_in[14];
    const float* proj_b   = (const float*)d_in[15];
    const int*   rel_idx  = (const int*)d_in[16];
    float* out = (float*)d_out;

    cudaFuncSetAttribute(fused_attn_kernel,
                         cudaFuncAttributeMaxDynamicSharedMemorySize,
                         SMEM_FLOATS * 4);

    bias_pre_kernel<<<192, 256>>>(rpb_x, rpb_y, rel_idx);
    fused_attn_kernel<<<2048, NT, SMEM_FLOATS * 4>>>(
        x, y, mask_x, mask_y, qkv_w, qkv_b, kv_w, kv_b,
        merge1_w, merge1_b, merge2_w, merge2_b, proj_w, proj_b, out);
}

// round 5
// speedup vs baseline: 2.0253x; 2.0253x over previous
#include <cuda_runtime.h>

#define NT 256
#define PA 194            // pitch for A, Q, K, V (even -> 8B aligned pairs)
#define PS 65             // S pitch
#define PW 26             // W stage pitch (24-col chunks)

#define OFF_A   0         // 64 x PA : X/Y, then per-head O, then relu(M)
#define OFF_Q   12416     // 64 x PA : scaled Q (persists both branches), then merge2 out T
#define OFF_K   24832     // 64 x PA : full K (per branch)
#define OFF_V   37248     // 64 x PA : full V (per branch)
#define OFF_S   49664     // 64 x PS  (also W stage buffer 1 during GEMM phases)
#define OFF_W0  53824     // 96 x PW = 2496 : W stage buffer 0
#define OFF_W1  OFF_S
#define SMEM_FLOATS 56320 // 225280 bytes

typedef unsigned long long u64;

static __device__ __forceinline__ u64 pk2(float lo, float hi) {
    u64 r; asm("mov.b64 %0,{%1,%2};" : "=l"(r) : "f"(lo), "f"(hi)); return r;
}
static __device__ __forceinline__ void upk2(u64 v, float& lo, float& hi) {
    asm("mov.b64 {%0,%1}, %2;" : "=f"(lo), "=f"(hi) : "l"(v));
}
static __device__ __forceinline__ void fma2(u64& d, u64 a, u64 b) {
    asm("fma.rn.f32x2 %0, %1, %2, %0;" : "+l"(d) : "l"(a), "l"(b));
}

__device__ float g_bias[2 * 6 * 64 * 64];

__global__ void bias_pre_kernel(const float* __restrict__ rpb_x,
                                const float* __restrict__ rpb_y,
                                const int* __restrict__ rel_idx) {
    int i = blockIdx.x * blockDim.x + threadIdx.x;
    if (i >= 2 * 6 * 4096) return;
    int br = i / (6 * 4096);
    int h  = (i / 4096) % 6;
    int nm = i & 4095;
    const float* tab = br ? rpb_y : rpb_x;
    g_bias[i] = tab[rel_idx[nm] * 6 + h];
}

// 64x192 GEMM: dst[n][o] = sum_c src[n][c] * W[o][c] (+bias)*scl.
// src at pitch PA in SMEM (reduction c contiguous). W row-major [o][ldw].
// Double-buffered 24-col W chunks with register prefetch: 1 sync per chunk,
// W LDG latency hidden behind compute.
// DST: 0 -> SMEM (pitch PA), 1 -> global (pitch 192), 2 -> accumulate into M (no bias).
template<int DST>
static __device__ __forceinline__ void wide_gemm(
    float* sm, int srcOff, const float* __restrict__ Wg, int ldw,
    const float* __restrict__ bg, float scl,
    float* dstS, float* __restrict__ dstG, float (*M)[6], int t)
{
    const int tr = t >> 5, tc = t & 31, n0 = tr * 8;
    int wbase[9], soff[9];
    #pragma unroll
    for (int k = 0; k < 9; ++k) {
        int e = k * NT + t;
        int jj = e / 24, dd = e - jj * 24;
        wbase[k] = jj * ldw + dd;
        soff[k]  = jj * PW + dd;
    }
    #pragma unroll 1
    for (int half = 0; half < 2; ++half) {
        const float* Wh = Wg + (size_t)half * 96 * ldw;
        u64 acc[8][3];
        #pragma unroll
        for (int i = 0; i < 8; ++i) { acc[i][0] = 0; acc[i][1] = 0; acc[i][2] = 0; }

        float pre[9];
        #pragma unroll
        for (int k = 0; k < 9; ++k) pre[k] = Wh[wbase[k]];
        #pragma unroll
        for (int k = 0; k < 9; ++k) sm[OFF_W0 + soff[k]] = pre[k];
        __syncthreads();

        #pragma unroll 1
        for (int ch = 0; ch < 8; ++ch) {
            if (ch < 7) {
                #pragma unroll
                for (int k = 0; k < 9; ++k) pre[k] = Wh[wbase[k] + (ch + 1) * 24];
            }
            const float* sa = sm + srcOff + ch * 24;
            const float* wb = sm + ((ch & 1) ? OFF_W1 : OFF_W0);
            #pragma unroll
            for (int dp = 0; dp < 12; ++dp) {
                u64 a2[8], w2[3];
                #pragma unroll
                for (int i = 0; i < 8; ++i)
                    a2[i] = *reinterpret_cast<const u64*>(&sa[(n0 + i) * PA + 2 * dp]);
                #pragma unroll
                for (int j = 0; j < 3; ++j)
                    w2[j] = *reinterpret_cast<const u64*>(&wb[(tc * 3 + j) * PW + 2 * dp]);
                #pragma unroll
                for (int i = 0; i < 8; ++i)
                    #pragma unroll
                    for (int j = 0; j < 3; ++j)
                        fma2(acc[i][j], a2[i], w2[j]);
            }
            if (ch < 7) {
                float* nb = sm + ((ch & 1) ? OFF_W0 : OFF_W1);
                #pragma unroll
                for (int k = 0; k < 9; ++k) nb[soff[k]] = pre[k];
            }
            __syncthreads();
        }

        #pragma unroll
        for (int j = 0; j < 3; ++j) {
            const int o = half * 96 + tc * 3 + j;
            #pragma unroll
            for (int i = 0; i < 8; ++i) {
                float lo, hi; upk2(acc[i][j], lo, hi);
                if (DST == 2) {
                    M[i][half * 3 + j] += lo + hi;
                } else {
                    float v = (lo + hi + bg[o]) * scl;
                    if (DST == 1) dstG[(n0 + i) * 192 + o] = v;
                    else          dstS[(n0 + i) * PA + o] = v;
                }
            }
        }
    }
}

__global__ void __launch_bounds__(NT, 1) fused_attn_kernel(
    const float* __restrict__ x, const float* __restrict__ y,
    const float* __restrict__ mask_x, const float* __restrict__ mask_y,
    const float* __restrict__ qkv_w, const float* __restrict__ qkv_b,
    const float* __restrict__ kv_w, const float* __restrict__ kv_b,
    const float* __restrict__ merge1_w, const float* __restrict__ merge1_b,
    const float* __restrict__ merge2_w, const float* __restrict__ merge2_b,
    const float* __restrict__ proj_w, const float* __restrict__ proj_b,
    float* __restrict__ out)
{
    extern __shared__ float sm[];
    const int t = threadIdx.x;
    const int w = blockIdx.x;
    const int tr = t >> 5, tc = t & 31;
    const int n0 = tr * 8;
    const float scale = 0.17677669529663687f;  // 32^-0.5

    // merge1 accumulator in registers; col = half*96 + tc*3 + j
    float M[8][6];
    #pragma unroll
    for (int half = 0; half < 2; ++half)
        #pragma unroll
        for (int j = 0; j < 3; ++j) {
            float b = merge1_b[half * 96 + tc * 3 + j];
            #pragma unroll
            for (int i = 0; i < 8; ++i) M[i][half * 3 + j] = b;
        }

    #pragma unroll 1
    for (int br = 0; br < 2; ++br) {
        // ---- load activation (X or Y) into A ----
        {
            const float* ap = (br ? y : x) + (size_t)w * 12288;
            for (int i = t; i < 12288; i += NT) {
                int n = i / 192, c = i - n * 192;
                sm[OFF_A + n * PA + c] = ap[i];
            }
        }
        // wide_gemm's first internal sync orders the A stores before reads.
        if (br == 0) {
            wide_gemm<0>(sm, OFF_A, qkv_w,              192, qkv_b,       scale, sm + OFF_Q, nullptr, nullptr, t);
            wide_gemm<0>(sm, OFF_A, qkv_w + 192 * 192,  192, qkv_b + 192, 1.f,   sm + OFF_K, nullptr, nullptr, t);
            wide_gemm<0>(sm, OFF_A, qkv_w + 384 * 192,  192, qkv_b + 384, 1.f,   sm + OFF_V, nullptr, nullptr, t);
        } else {
            wide_gemm<0>(sm, OFF_A, kv_w,               192, kv_b,        1.f,   sm + OFF_K, nullptr, nullptr, t);
            wide_gemm<0>(sm, OFF_A, kv_w + 192 * 192,   192, kv_b + 192,  1.f,   sm + OFF_V, nullptr, nullptr, t);
        }
        __syncthreads();   // epilogue Q/K/V stores -> visible to attention phases

        const float* bias_base = g_bias + (size_t)(br * 6) * 4096;
        const float* maskp = (br ? mask_y : mask_x) + (size_t)(w & 1023) * 4096;

        #pragma unroll 1
        for (int h = 0; h < 6; ++h) {
            const int h32 = h * 32;

            // ---- S = Q K^T + bias + mask  (8x2 tiles, fma2 over d) ----
            {
                const int m0 = tc * 2;
                float bi[8][2], mk[8][2];
                const float* bb = bias_base + h * 4096;
                #pragma unroll
                for (int i = 0; i < 8; ++i)
                    #pragma unroll
                    for (int j = 0; j < 2; ++j) {
                        bi[i][j] = bb[(n0 + i) * 64 + m0 + j];
                        mk[i][j] = maskp[(n0 + i) * 64 + m0 + j];
                    }
                u64 acc[8][2];
                #pragma unroll
                for (int i = 0; i < 8; ++i) { acc[i][0] = 0; acc[i][1] = 0; }
                #pragma unroll
                for (int dp = 0; dp < 16; ++dp) {
                    u64 q2[8], k2[2];
                    #pragma unroll
                    for (int i = 0; i < 8; ++i)
                        q2[i] = *reinterpret_cast<const u64*>(
                            &sm[OFF_Q + (n0 + i) * PA + h32 + 2 * dp]);
                    #pragma unroll
                    for (int j = 0; j < 2; ++j)
                        k2[j] = *reinterpret_cast<const u64*>(
                            &sm[OFF_K + (m0 + j) * PA + h32 + 2 * dp]);
                    #pragma unroll
                    for (int i = 0; i < 8; ++i)
                        #pragma unroll
                        for (int j = 0; j < 2; ++j)
                            fma2(acc[i][j], q2[i], k2[j]);
                }
                #pragma unroll
                for (int i = 0; i < 8; ++i)
                    #pragma unroll
                    for (int j = 0; j < 2; ++j) {
                        float lo, hi; upk2(acc[i][j], lo, hi);
                        sm[OFF_S + (n0 + i) * PS + m0 + j] = lo + hi + bi[i][j] + mk[i][j];
                    }
            }
            __syncthreads();

            // ---- softmax per row (warp handles 8 rows) ----
            {
                const int wi = t >> 5, l = t & 31;
                #pragma unroll
                for (int rr = 0; rr < 8; rr++) {
                    int r = wi * 8 + rr;
                    float v0 = sm[OFF_S + r * PS + l];
                    float v1 = sm[OFF_S + r * PS + 32 + l];
                    float mx = fmaxf(v0, v1);
                    #pragma unroll
                    for (int o = 16; o > 0; o >>= 1)
                        mx = fmaxf(mx, __shfl_xor_sync(0xffffffffu, mx, o));
                    float e0 = __expf(v0 - mx), e1 = __expf(v1 - mx);
                    float s = e0 + e1;
                    #pragma unroll
                    for (int o = 16; o > 0; o >>= 1)
                        s += __shfl_xor_sync(0xffffffffu, s, o);
                    float inv = 1.0f / s;
                    sm[OFF_S + r * PS + l]      = e0 * inv;
                    sm[OFF_S + r * PS + 32 + l] = e1 * inv;
                }
            }
            __syncthreads();

            // ---- O_h = P V_h  -> A region at col h*32 (A is dead) ----
            {
                const int n0p = (t >> 4) * 4, d0 = (t & 15) * 2;
                u64 acc[4];
                #pragma unroll
                for (int i = 0; i < 4; ++i) acc[i] = 0;
                #pragma unroll 4
                for (int m = 0; m < 64; ++m) {
                    u64 v2 = *reinterpret_cast<const u64*>(
                        &sm[OFF_V + m * PA + h32 + d0]);
                    #pragma unroll
                    for (int i = 0; i < 4; ++i) {
                        float p = sm[OFF_S + (n0p + i) * PS + m];
                        fma2(acc[i], pk2(p, p), v2);
                    }
                }
                #pragma unroll
                for (int i = 0; i < 4; ++i)
                    *reinterpret_cast<u64*>(&sm[OFF_A + (n0p + i) * PA + h32 + d0]) = acc[i];
            }
            __syncthreads();
        }  // heads

        // ---- merge1: M += O_all @ W1_branch^T  (one wide GEMM, red=192) ----
        wide_gemm<2>(sm, OFF_A, merge1_w + br * 192, 384, nullptr, 1.f,
                     nullptr, nullptr, M, t);
        // ends with a full barrier -> safe to overwrite A next branch
    }  // branches

    // ---- leaky relu(M) -> A (dead) ----
    #pragma unroll
    for (int half = 0; half < 2; ++half)
        #pragma unroll
        for (int j = 0; j < 3; ++j)
            #pragma unroll
            for (int i = 0; i < 8; ++i) {
                float v = M[i][half * 3 + j];
                v = v > 0.f ? v : 0.2f * v;
                sm[OFF_A + (n0 + i) * PA + half * 96 + tc * 3 + j] = v;
            }
    // merge2: T = relu(M) @ W2^T + b2 -> Q region (internal first sync orders A stores)
    wide_gemm<0>(sm, OFF_A, merge2_w, 192, merge2_b, 1.f, sm + OFF_Q, nullptr, nullptr, t);
    // proj: out = T @ Wp^T + pb -> global (internal first sync orders Q stores)
    wide_gemm<1>(sm, OFF_Q, proj_w, 192, proj_b, 1.f, nullptr,
                 out + (size_t)w * 12288, nullptr, t);
}

extern "C" void kernel_launch(void* const* d_in, const int* in_sizes, int n_in,
                              void* d_out, int out_size) {
    const float* x        = (const float*)d_in[0];
    const float* y        = (const float*)d_in[1];
    const float* mask_x   = (const float*)d_in[2];
    const float* mask_y   = (const float*)d_in[3];
    const float* qkv_w    = (const float*)d_in[4];
    const float* qkv_b    = (const float*)d_in[5];
    const float* kv_w     = (const float*)d_in[6];
    const float* kv_b     = (const float*)d_in[7];
    const float* rpb_x    = (const float*)d_in[8];
    const float* rpb_y    = (const float*)d_in[9];
    const float* merge1_w = (const float*)d_in[10];
    const float* merge1_b = (const float*)d_in[11];
    const float* merge2_w = (const float*)d_in[12];
    const float* merge2_b = (const float*)d_in[13];
    const float* proj_w   = (const float*)d_in[14];
    const float* proj_b   = (const float*)d_in[15];
    const int*   rel_idx  = (const int*)d_in[16];
    float* out = (float*)d_out;

    cudaFuncSetAttribute(fused_attn_kernel,
                         cudaFuncAttributeMaxDynamicSharedMemorySize,
                         SMEM_FLOATS * 4);

    bias_pre_kernel<<<192, 256>>>(rpb_x, rpb_y, rel_idx);
    fused_attn_kernel<<<2048, NT, SMEM_FLOATS * 4>>>(
        x, y, mask_x, mask_y, qkv_w, qkv_b, kv_w, kv_b,
        merge1_w, merge1_b, merge2_w, merge2_b, proj_w, proj_b, out);
}